// round 11
// baseline (speedup 1.0000x reference)
#include <cuda_runtime.h>
#include <math.h>
#include <stdint.h>

// Problem constants: B=4, L=1024, H=512, NH=8, HD=64, rel rows = 2048

__device__ float g_rel[2048 * 64];            // rel[t][d]
__device__ float g_relD[8 * 2048];            // delta_n . rel_t
__device__ float g_q[4 * 8 * 1024 * 64];      // [b][n][l][d]
__device__ float g_v[4 * 8 * 1024 * 64];

// ---------------------------------------------------------------------------
// Kernel 1: rel[t][d] = emb(t) @ w_r_w + w_r_b   (proven)
// ---------------------------------------------------------------------------
__global__ void __launch_bounds__(256) rel_kernel(const float* __restrict__ w_r_w,
                                                  const float* __restrict__ w_r_b) {
    extern __shared__ float rsm[];
    float* Wsm = rsm;            // 512*64
    float* Emb = Wsm + 32768;    // 8*512

    const int tid = threadIdx.x;
    const int r0 = blockIdx.x * 8;
    const float cc = (float)(-9.210340371976184 / 255.0);

    for (int idx = tid * 4; idx < 32768; idx += 1024)
        *(float4*)&Wsm[idx] = *(const float4*)&w_r_w[idx];

    for (int idx = tid; idx < 8 * 512; idx += 256) {
        int row = idx >> 9;
        int h = idx & 511;
        int t = (h < 256) ? h : (h - 256);
        float f = expf((float)t * cc);
        float ang = (float)(r0 + row - 1024) * f;
        Emb[idx] = (h < 256) ? sinf(ang) : cosf(ang);
    }
    __syncthreads();

    const int d = tid & 63;
    const int rl = tid >> 6;
    const float bias = w_r_b[d];
    #pragma unroll
    for (int rr = 0; rr < 2; rr++) {
        int row = rl + 4 * rr;
        float sum = bias;
        const float* e = &Emb[row * 512];
        #pragma unroll 8
        for (int h = 0; h < 512; h++)
            sum = fmaf(e[h], Wsm[h * 64 + d], sum);
        g_rel[(size_t)(r0 + row) * 64 + d] = sum;
    }
}

// ---------------------------------------------------------------------------
// Kernel 1b: g_relD[n][t] = (r_w_bias[n] - r_r_bias[n]) . g_rel[t]
// ---------------------------------------------------------------------------
__global__ void __launch_bounds__(256) reld_kernel(const float* __restrict__ rr_bias,
                                                   const float* __restrict__ rw_bias) {
    __shared__ float relS[32 * 64];
    __shared__ float dS[8 * 64];
    const int tid = threadIdx.x;
    const int t0 = blockIdx.x * 32;

    for (int i = tid; i < 512; i += 256)
        dS[i] = rw_bias[i] - rr_bias[i];
    for (int i = tid * 4; i < 2048; i += 1024)
        *(float4*)&relS[i] = *(const float4*)&g_rel[(size_t)t0 * 64 + i];
    __syncthreads();

    const int tl = tid >> 3, n = tid & 7;
    const float* dn = &dS[n * 64];
    const float* rrow = &relS[tl * 64];
    float s = 0.f;
    #pragma unroll 16
    for (int d = 0; d < 64; d++)
        s = fmaf(dn[d], rrow[d], s);
    g_relD[n * 2048 + t0 + tl] = s;
}

// ---------------------------------------------------------------------------
// Kernel 2: projections (proven R5 SGEMM)
// ---------------------------------------------------------------------------
__global__ void __launch_bounds__(256) proj_kernel(
    const float* __restrict__ q_in, const float* __restrict__ v_in,
    const float* __restrict__ wq, const float* __restrict__ bq,
    const float* __restrict__ wv, const float* __restrict__ bv) {

    const float* X;  const float* W;  const float* bias;  float* out;
    if (blockIdx.z == 0) { X = q_in; W = wq; bias = bq; out = g_q; }
    else                 { X = v_in; W = wv; bias = bv; out = g_v; }

    __shared__ float As[64][16];
    __shared__ float Bs[16][64];

    const int tid = threadIdx.x;
    const int tx = tid & 15, ty = tid >> 4;
    const int m0 = blockIdx.y * 64;
    const int n0 = blockIdx.x * 64;

    float acc[4][4] = {};

    for (int k0 = 0; k0 < 512; k0 += 16) {
        float4 av = *(const float4*)&X[(size_t)(m0 + (tid >> 2)) * 512 + k0 + (tid & 3) * 4];
        *(float4*)&As[tid >> 2][(tid & 3) * 4] = av;
        float4 bv4 = *(const float4*)&W[(size_t)(k0 + (tid >> 4)) * 512 + n0 + (tid & 15) * 4];
        *(float4*)&Bs[tid >> 4][(tid & 15) * 4] = bv4;
        __syncthreads();

        #pragma unroll
        for (int kk = 0; kk < 16; kk++) {
            float a[4];
            #pragma unroll
            for (int r = 0; r < 4; r++) a[r] = As[ty * 4 + r][kk];
            float4 b4 = *(const float4*)&Bs[kk][tx * 4];
            float b[4] = { b4.x, b4.y, b4.z, b4.w };
            #pragma unroll
            for (int r = 0; r < 4; r++)
                #pragma unroll
                for (int cc = 0; cc < 4; cc++)
                    acc[r][cc] = fmaf(a[r], b[cc], acc[r][cc]);
        }
        __syncthreads();
    }

    float4 bb = *(const float4*)&bias[n0 + tx * 4];
    const int n = blockIdx.x;
    #pragma unroll
    for (int r = 0; r < 4; r++) {
        int m = m0 + ty * 4 + r;
        int b = m >> 10, l = m & 1023;
        float4 o;
        o.x = acc[r][0] + bb.x;  o.y = acc[r][1] + bb.y;
        o.z = acc[r][2] + bb.z;  o.w = acc[r][3] + bb.w;
        *(float4*)&out[(size_t)((b * 8 + n) * 1024 + l) * 64 + tx * 4] = o;
    }
}

// ---------------------------------------------------------------------------
// Kernel 3: fused attention. 512 threads, d-split halves, DIAGONAL lane map:
//   ty = lane&15, class = 2*warp + (lane>>4), tx = (ty+class)&15.
// Band rows per half-warp are uniform -> LDS broadcast (1 wavefront).
// RB/RE stored with CUMULATIVE +8-word pad per 16-row block (no overlap;
// rows 16 apart land 8 banks apart instead of 0).
// Softmax row-reduction via smem partial buffers (stride 17).
// ---------------------------------------------------------------------------
__global__ void __launch_bounds__(512, 1) attn_kernel(
    const float* __restrict__ key,
    const float* __restrict__ r_r_bias,
    const int*   __restrict__ seq_len_p,
    float* __restrict__ out) {

    extern __shared__ float sm[];
    float* QA  = sm;                 //  64 x 66            [0,      4224)
    float* Ks  = QA + 4224;          //  64 x 66            [4224,   8448)
    float* Pm  = Ks + 4224;          //  64 x 66            [8448,  12672)
    float* RB  = Pm + 4224;          // 128 x 66 + cum pad  [12672, 21184)
    float* RE  = RB + 8512;          // 128 x 66 + cum pad  [21184, 29696)
    float* Vs  = RE + 8512;          //  64 x 64            [29696, 33792)
    float* scS = Vs + 4096;          //  64                 [33792, 33856)
    float* pmS = scS + 64;           //  64 x 17            [33856, 34944)
    float* psS = pmS + 1088;         //  64 x 17            [34944, 36032)

    const int tid = threadIdx.x;
    const int h = tid >> 8;             // d-half
    const int lam = tid & 31;
    const int w8 = (tid >> 5) & 7;      // warp within half
    const int ty = lam & 15;
    const int cls = 2 * w8 + (lam >> 4);        // 0..15, const per half-warp
    const int tx = (ty + cls) & 15;
    const int diag = tx - ty;                   // cls or cls-16
    const int tx4 = tx * 4;
    const int dOff = h * 32;
    const int i0 = blockIdx.x * 64;
    const int bn = blockIdx.y;
    const int b = bn >> 3, n = bn & 7;
    const int seq = *seq_len_p;

    const float* qptr = g_q + (size_t)bn * 1024 * 64;
    const float* vptr = g_v + (size_t)bn * 1024 * 64;
    const float* kptr = key + (size_t)b * 1024 * 512 + n * 64;
    const float* relD = g_relD + n * 2048;

    // QA = q + r_r_bias
    for (int idx = tid; idx < 1024; idx += 512) {
        int i = idx >> 4; int d4 = (idx & 15) << 2;
        float4 q4 = *(const float4*)&qptr[(size_t)(i0 + i) * 64 + d4];
        float4 rr = *(const float4*)&r_r_bias[n * 64 + d4];
        float* pa = &QA[i * 66 + d4];
        *(float2*)&pa[0] = make_float2(q4.x + rr.x, q4.y + rr.y);
        *(float2*)&pa[2] = make_float2(q4.z + rr.z, q4.w + rr.w);
    }

    float m_r[4], l_r[4], acc[4][4];
    #pragma unroll
    for (int r = 0; r < 4; r++) {
        m_r[r] = -INFINITY; l_r[r] = 0.f;
        acc[r][0] = acc[r][1] = acc[r][2] = acc[r][3] = 0.f;
    }

    // band buffer offsets (CUMULATIVE pad: +8 words per 16-row block); d folded in
    int offB[7], offE[7];
    #pragma unroll
    for (int m = 0; m < 7; m++) {
        int uB = diag + 15 + 16 * m;            // in [0,126]
        int uE = -diag + 15 + 16 * m;
        offB[m] = uB * 66 + (uB >> 4) * 8 + dOff;
        offE[m] = uE * 66 + (uE >> 4) * 8 + dOff;
    }

    const float* pQA = QA + ty * 66 + dOff;
    const float* pK  = Ks + tx * 66 + dOff;

    for (int jt = 0; jt < 16; jt++) {
        const int j0 = jt * 64;
        __syncthreads();   // SYNC_A: prev PV done; first iter: QA ready

        // --- tile loads ---
        for (int idx = tid; idx < 1024; idx += 512) {
            int j = idx >> 4; int d4 = (idx & 15) << 2;
            float4 k4 = *(const float4*)&kptr[(size_t)(j0 + j) * 512 + d4];
            float* pk = &Ks[j * 66 + d4];
            *(float2*)&pk[0] = make_float2(k4.x, k4.y);
            *(float2*)&pk[2] = make_float2(k4.z, k4.w);
            float4 v4 = *(const float4*)&vptr[(size_t)(j0 + j) * 64 + d4];
            *(float4*)&Vs[j * 64 + d4] = v4;
        }
        const int rbBase = 1024 + j0 - i0 - 63;
        const int reBase = 1024 + i0 - j0 - 63;
        for (int idx = tid; idx < 2048; idx += 512) {
            int u = idx >> 4; int d4 = (idx & 15) << 2;
            int pad = (u >> 4) * 8;             // cumulative pad
            int rb_r = rbBase + u; rb_r = (rb_r > 2047) ? 2047 : rb_r;
            int re_r = reBase + u; re_r = (re_r > 2047) ? 2047 : re_r;
            float4 b4 = *(const float4*)&g_rel[(size_t)rb_r * 64 + d4];
            float* prb = &RB[u * 66 + pad + d4];
            *(float2*)&prb[0] = make_float2(b4.x, b4.y);
            *(float2*)&prb[2] = make_float2(b4.z, b4.w);
            float4 e4 = *(const float4*)&g_rel[(size_t)re_r * 64 + d4];
            float* pre = &RE[u * 66 + pad + d4];
            *(float2*)&pre[0] = make_float2(e4.x, e4.y);
            *(float2*)&pre[2] = make_float2(e4.z, e4.w);
        }
        __syncthreads();   // SYNC_B: tiles ready

        // --- fused AC + B + E partial score (this half's 32 d) ---
        float s[4][4] = {};
        #pragma unroll 2
        for (int d = 0; d < 32; d += 2) {
            float2 qa[4], k2[4], rb[7], re[7];
            #pragma unroll
            for (int r = 0; r < 4; r++) qa[r] = *(const float2*)&pQA[r * (16 * 66) + d];
            #pragma unroll
            for (int c = 0; c < 4; c++) k2[c] = *(const float2*)&pK[c * (16 * 66) + d];
            #pragma unroll
            for (int m = 0; m < 7; m++) {
                rb[m] = *(const float2*)&RB[offB[m] + d];
                re[m] = *(const float2*)&RE[offE[m] + d];
            }
            #pragma unroll
            for (int r = 0; r < 4; r++)
                #pragma unroll
                for (int c = 0; c < 4; c++) {
                    float t0 = fmaf(qa[r].x, k2[c].x, s[r][c]);
                    float t1 = fmaf(qa[r].y, k2[c].y, t0);
                    float t2 = fmaf(qa[r].x, rb[c - r + 3].x, t1);
                    float t3 = fmaf(qa[r].y, rb[c - r + 3].y, t2);
                    float t4 = fmaf(k2[c].x, re[r - c + 3].x, t3);
                    s[r][c]  = fmaf(k2[c].y, re[r - c + 3].y, t4);
                }
        }

        // half 1 publishes partials into Pm scratch
        if (h == 1) {
            #pragma unroll
            for (int r = 0; r < 4; r++) {
                float* prow = &Pm[(ty + 16 * r) * 66 + tx];
                #pragma unroll
                for (int c = 0; c < 4; c++) prow[16 * c] = s[r][c];
            }
        }
        __syncthreads();   // SYNC_C: partials visible

        float sc_r[4];
        if (h == 0) {
            float db[7];
            const float* pD = relD + (1024 + j0 - i0 + diag);
            #pragma unroll
            for (int m = 0; m < 7; m++) db[m] = pD[16 * (m - 3)];

            #pragma unroll
            for (int r = 0; r < 4; r++) {
                float* prow = &Pm[(ty + 16 * r) * 66 + tx];
                #pragma unroll
                for (int c = 0; c < 4; c++)
                    s[r][c] += prow[16 * c] + db[c - r + 3];
            }
            #pragma unroll
            for (int c = 0; c < 4; c++) {
                if (j0 + tx + 16 * c >= seq) {
                    s[0][c] = -1e30f; s[1][c] = -1e30f; s[2][c] = -1e30f; s[3][c] = -1e30f;
                }
            }
            // lane-local max over 4 cols -> partial buffer
            #pragma unroll
            for (int r = 0; r < 4; r++) {
                float lm = fmaxf(fmaxf(s[r][0], s[r][1]), fmaxf(s[r][2], s[r][3]));
                pmS[(ty + 16 * r) * 17 + cls] = lm;
            }
        }
        __syncthreads();   // SYNC_D1: max partials visible

        if (h == 0) {
            #pragma unroll
            for (int r = 0; r < 4; r++) {
                const float* pm = &pmS[(ty + 16 * r) * 17];
                float rm = pm[0];
                #pragma unroll
                for (int k = 1; k < 16; k++) rm = fmaxf(rm, pm[k]);
                float mnew = fmaxf(m_r[r], rm);
                sc_r[r] = __expf(m_r[r] - mnew);
                m_r[r] = mnew;
                float psum = 0.f;
                float* prow = &Pm[(ty + 16 * r) * 66 + tx];
                #pragma unroll
                for (int c = 0; c < 4; c++) {
                    float p = __expf(s[r][c] - mnew);
                    prow[16 * c] = p;
                    psum += p;
                }
                psS[(ty + 16 * r) * 17 + cls] = psum;
            }
        }
        __syncthreads();   // SYNC_D2: P + sum partials visible

        if (h == 0) {
            #pragma unroll
            for (int r = 0; r < 4; r++) {
                const float* ps = &psS[(ty + 16 * r) * 17];
                float rs = ps[0];
                #pragma unroll
                for (int k = 1; k < 16; k++) rs += ps[k];
                l_r[r] = l_r[r] * sc_r[r] + rs;
                acc[r][0] *= sc_r[r]; acc[r][1] *= sc_r[r];
                acc[r][2] *= sc_r[r]; acc[r][3] *= sc_r[r];
                if (cls == 0) scS[ty + 16 * r] = sc_r[r];
            }
        }
        __syncthreads();   // SYNC_E: scales visible

        if (h == 1) {
            #pragma unroll
            for (int r = 0; r < 4; r++) {
                float sc = scS[ty + 16 * r];
                acc[r][0] *= sc; acc[r][1] *= sc; acc[r][2] *= sc; acc[r][3] *= sc;
            }
        }

        // --- PV: this half's 32 jj ---
        const int jb = h * 32;
        #pragma unroll 2
        for (int jj = jb; jj < jb + 32; jj += 2) {
            float4 v0 = *(const float4*)&Vs[jj * 64 + tx4];
            float4 v1 = *(const float4*)&Vs[(jj + 1) * 64 + tx4];
            #pragma unroll
            for (int r = 0; r < 4; r++) {
                float2 p = *(const float2*)&Pm[(ty + 16 * r) * 66 + jj];
                acc[r][0] = fmaf(p.x, v0.x, acc[r][0]);
                acc[r][1] = fmaf(p.x, v0.y, acc[r][1]);
                acc[r][2] = fmaf(p.x, v0.z, acc[r][2]);
                acc[r][3] = fmaf(p.x, v0.w, acc[r][3]);
                acc[r][0] = fmaf(p.y, v1.x, acc[r][0]);
                acc[r][1] = fmaf(p.y, v1.y, acc[r][1]);
                acc[r][2] = fmaf(p.y, v1.z, acc[r][2]);
                acc[r][3] = fmaf(p.y, v1.w, acc[r][3]);
            }
        }
    }

    // epilogue: combine halves through Vs buffer, then scale by 1/l
    __syncthreads();
    if (h == 1) {
        #pragma unroll
        for (int r = 0; r < 4; r++)
            *(float4*)&Vs[(ty + 16 * r) * 64 + tx4] =
                make_float4(acc[r][0], acc[r][1], acc[r][2], acc[r][3]);
    }
    __syncthreads();
    if (h == 0) {
        #pragma unroll
        for (int r = 0; r < 4; r++) {
            float inv = 1.0f / l_r[r];
            float4 a2 = *(const float4*)&Vs[(ty + 16 * r) * 64 + tx4];
            int row = i0 + ty + 16 * r;
            float4 o;
            o.x = (acc[r][0] + a2.x) * inv; o.y = (acc[r][1] + a2.y) * inv;
            o.z = (acc[r][2] + a2.z) * inv; o.w = (acc[r][3] + a2.w) * inv;
            *(float4*)&out[(size_t)(b * 1024 + row) * 512 + n * 64 + tx4] = o;
        }
    }
}

// ---------------------------------------------------------------------------
extern "C" void kernel_launch(void* const* d_in, const int* in_sizes, int n_in,
                              void* d_out, int out_size) {
    const float* query    = (const float*)d_in[0];
    const float* key      = (const float*)d_in[1];
    const float* value    = (const float*)d_in[2];
    const float* w_q_w    = (const float*)d_in[3];
    const float* w_q_b    = (const float*)d_in[4];
    const float* w_v_w    = (const float*)d_in[5];
    const float* w_v_b    = (const float*)d_in[6];
    const float* w_r_w    = (const float*)d_in[7];
    const float* w_r_b    = (const float*)d_in[8];
    const float* r_r_bias = (const float*)d_in[9];
    const float* r_w_bias = (const float*)d_in[10];
    const int*   seq_len  = (const int*)d_in[11];
    float* out = (float*)d_out;

    const int rel_smem = (32768 + 4096) * 4;   // 147456
    cudaFuncSetAttribute(rel_kernel, cudaFuncAttributeMaxDynamicSharedMemorySize, rel_smem);
    rel_kernel<<<256, 256, rel_smem>>>(w_r_w, w_r_b);
    reld_kernel<<<64, 256>>>(r_r_bias, r_w_bias);

    proj_kernel<<<dim3(8, 64, 2), 256>>>(query, value, w_q_w, w_q_b, w_v_w, w_v_b);

    const int attn_smem = 36032 * 4;   // 144128
    cudaFuncSetAttribute(attn_kernel, cudaFuncAttributeMaxDynamicSharedMemorySize, attn_smem);
    attn_kernel<<<dim3(16, 32), 512, attn_smem>>>(key, r_r_bias, seq_len, out);
}

// round 12
// speedup vs baseline: 1.1815x; 1.1815x over previous
#include <cuda_runtime.h>
#include <math.h>
#include <stdint.h>

typedef unsigned long long ull;

// Problem constants: B=4, L=1024, H=512, NH=8, HD=64, rel rows = 2048

__device__ float g_rel[2048 * 64];            // rel[t][d]
__device__ float g_relD[8 * 2048];            // delta_n . rel_t
__device__ float g_q[4 * 8 * 1024 * 64];      // [b][n][l][d]
__device__ float g_v[4 * 8 * 1024 * 64];

// ---------------------------------------------------------------------------
// Packed fp32x2 helpers (PTX baseline for sm_100+; FFMA2 in SASS)
// ---------------------------------------------------------------------------
__device__ __forceinline__ ull fma2(ull a, ull b, ull c) {
    ull d;
    asm("fma.rn.f32x2 %0, %1, %2, %3;" : "=l"(d) : "l"(a), "l"(b), "l"(c));
    return d;
}
__device__ __forceinline__ ull mul2(ull a, ull b) {
    ull d;
    asm("mul.rn.f32x2 %0, %1, %2;" : "=l"(d) : "l"(a), "l"(b));
    return d;
}
__device__ __forceinline__ ull pack2(float x, float y) {
    ull d;
    asm("mov.b64 %0, {%1, %2};" : "=l"(d) : "f"(x), "f"(y));
    return d;
}
__device__ __forceinline__ float2 unpack2(ull a) {
    float x, y;
    asm("mov.b64 {%0, %1}, %2;" : "=f"(x), "=f"(y) : "l"(a));
    return make_float2(x, y);
}

// ---------------------------------------------------------------------------
// Kernel 1: rel[t][d] = emb(t) @ w_r_w + w_r_b   (proven)
// ---------------------------------------------------------------------------
__global__ void __launch_bounds__(256) rel_kernel(const float* __restrict__ w_r_w,
                                                  const float* __restrict__ w_r_b) {
    extern __shared__ float rsm[];
    float* Wsm = rsm;            // 512*64
    float* Emb = Wsm + 32768;    // 8*512

    const int tid = threadIdx.x;
    const int r0 = blockIdx.x * 8;
    const float cc = (float)(-9.210340371976184 / 255.0);

    for (int idx = tid * 4; idx < 32768; idx += 1024)
        *(float4*)&Wsm[idx] = *(const float4*)&w_r_w[idx];

    for (int idx = tid; idx < 8 * 512; idx += 256) {
        int row = idx >> 9;
        int h = idx & 511;
        int t = (h < 256) ? h : (h - 256);
        float f = expf((float)t * cc);
        float ang = (float)(r0 + row - 1024) * f;
        Emb[idx] = (h < 256) ? sinf(ang) : cosf(ang);
    }
    __syncthreads();

    const int d = tid & 63;
    const int rl = tid >> 6;
    const float bias = w_r_b[d];
    #pragma unroll
    for (int rr = 0; rr < 2; rr++) {
        int row = rl + 4 * rr;
        float sum = bias;
        const float* e = &Emb[row * 512];
        #pragma unroll 8
        for (int h = 0; h < 512; h++)
            sum = fmaf(e[h], Wsm[h * 64 + d], sum);
        g_rel[(size_t)(r0 + row) * 64 + d] = sum;
    }
}

// ---------------------------------------------------------------------------
// Kernel 1b: g_relD[n][t] = (r_w_bias[n] - r_r_bias[n]) . g_rel[t]
// ---------------------------------------------------------------------------
__global__ void __launch_bounds__(256) reld_kernel(const float* __restrict__ rr_bias,
                                                   const float* __restrict__ rw_bias) {
    __shared__ float relS[32 * 64];
    __shared__ float dS[8 * 64];
    const int tid = threadIdx.x;
    const int t0 = blockIdx.x * 32;

    for (int i = tid; i < 512; i += 256)
        dS[i] = rw_bias[i] - rr_bias[i];
    for (int i = tid * 4; i < 2048; i += 1024)
        *(float4*)&relS[i] = *(const float4*)&g_rel[(size_t)t0 * 64 + i];
    __syncthreads();

    const int tl = tid >> 3, n = tid & 7;
    const float* dn = &dS[n * 64];
    const float* rrow = &relS[tl * 64];
    float s = 0.f;
    #pragma unroll 16
    for (int d = 0; d < 64; d++)
        s = fmaf(dn[d], rrow[d], s);
    g_relD[n * 2048 + t0 + tl] = s;
}

// ---------------------------------------------------------------------------
// Kernel 2: projections (proven R5 SGEMM)
// ---------------------------------------------------------------------------
__global__ void __launch_bounds__(256) proj_kernel(
    const float* __restrict__ q_in, const float* __restrict__ v_in,
    const float* __restrict__ wq, const float* __restrict__ bq,
    const float* __restrict__ wv, const float* __restrict__ bv) {

    const float* X;  const float* W;  const float* bias;  float* out;
    if (blockIdx.z == 0) { X = q_in; W = wq; bias = bq; out = g_q; }
    else                 { X = v_in; W = wv; bias = bv; out = g_v; }

    __shared__ float As[64][16];
    __shared__ float Bs[16][64];

    const int tid = threadIdx.x;
    const int tx = tid & 15, ty = tid >> 4;
    const int m0 = blockIdx.y * 64;
    const int n0 = blockIdx.x * 64;

    float acc[4][4] = {};

    for (int k0 = 0; k0 < 512; k0 += 16) {
        float4 av = *(const float4*)&X[(size_t)(m0 + (tid >> 2)) * 512 + k0 + (tid & 3) * 4];
        *(float4*)&As[tid >> 2][(tid & 3) * 4] = av;
        float4 bv4 = *(const float4*)&W[(size_t)(k0 + (tid >> 4)) * 512 + n0 + (tid & 15) * 4];
        *(float4*)&Bs[tid >> 4][(tid & 15) * 4] = bv4;
        __syncthreads();

        #pragma unroll
        for (int kk = 0; kk < 16; kk++) {
            float a[4];
            #pragma unroll
            for (int r = 0; r < 4; r++) a[r] = As[ty * 4 + r][kk];
            float4 b4 = *(const float4*)&Bs[kk][tx * 4];
            float b[4] = { b4.x, b4.y, b4.z, b4.w };
            #pragma unroll
            for (int r = 0; r < 4; r++)
                #pragma unroll
                for (int cc = 0; cc < 4; cc++)
                    acc[r][cc] = fmaf(a[r], b[cc], acc[r][cc]);
        }
        __syncthreads();
    }

    float4 bb = *(const float4*)&bias[n0 + tx * 4];
    const int n = blockIdx.x;
    #pragma unroll
    for (int r = 0; r < 4; r++) {
        int m = m0 + ty * 4 + r;
        int b = m >> 10, l = m & 1023;
        float4 o;
        o.x = acc[r][0] + bb.x;  o.y = acc[r][1] + bb.y;
        o.z = acc[r][2] + bb.z;  o.w = acc[r][3] + bb.w;
        *(float4*)&out[(size_t)((b * 8 + n) * 1024 + l) * 64 + tx * 4] = o;
    }
}

// ---------------------------------------------------------------------------
// Kernel 3: fused attention (R9 structure: 512 threads, d-split halves,
// strided (tx,ty) fragment map) with packed fp32x2 (FFMA2) math in the
// score pass and PV.
// ---------------------------------------------------------------------------
__global__ void __launch_bounds__(512, 1) attn_kernel(
    const float* __restrict__ key,
    const float* __restrict__ r_r_bias,
    const int*   __restrict__ seq_len_p,
    float* __restrict__ out) {

    extern __shared__ float sm[];
    float* QA  = sm;                 // 64 x 66
    float* Ks  = QA + 64 * 66;       // 64 x 66
    float* Pm  = Ks + 64 * 66;       // 64 x 66  (also score-partial scratch)
    float* RB  = Pm + 64 * 66;       // 128 x 66
    float* RE  = RB + 128 * 66;      // 128 x 66
    float* Vs  = RE + 128 * 66;      // 64 x 64  (also epilogue acc buffer)
    float* scS = Vs + 64 * 64;       // 64       (per-row scale broadcast)

    const int tid = threadIdx.x;
    const int h = tid >> 8;             // 0: warps 0-7, 1: warps 8-15
    const int t = tid & 255;
    const int tx = t & 15, ty = t >> 4;
    const int tx4 = tx * 4;
    const int dOff = h * 32;
    const int i0 = blockIdx.x * 64;
    const int bn = blockIdx.y;
    const int b = bn >> 3, n = bn & 7;
    const int seq = *seq_len_p;

    const float* qptr = g_q + (size_t)bn * 1024 * 64;
    const float* vptr = g_v + (size_t)bn * 1024 * 64;
    const float* kptr = key + (size_t)b * 1024 * 512 + n * 64;
    const float* relD = g_relD + n * 2048;

    // QA = q + r_r_bias
    for (int idx = tid; idx < 1024; idx += 512) {
        int i = idx >> 4; int d4 = (idx & 15) << 2;
        float4 q4 = *(const float4*)&qptr[(size_t)(i0 + i) * 64 + d4];
        float4 rr = *(const float4*)&r_r_bias[n * 64 + d4];
        float* pa = &QA[i * 66 + d4];
        *(float2*)&pa[0] = make_float2(q4.x + rr.x, q4.y + rr.y);
        *(float2*)&pa[2] = make_float2(q4.z + rr.z, q4.w + rr.w);
    }

    float m_r[4], l_r[4];
    ull acc2[4][2];                    // packed: [r][0]=(d0,d1), [r][1]=(d2,d3)
    #pragma unroll
    for (int r = 0; r < 4; r++) {
        m_r[r] = -INFINITY; l_r[r] = 0.f;
        acc2[r][0] = 0ULL; acc2[r][1] = 0ULL;
    }

    const int baseB = tx - ty + 63;
    const int baseE = ty - tx + 63;

    const float* pQA = QA + ty * 66 + dOff;
    const float* pK  = Ks + tx * 66 + dOff;
    const float* pRB = RB + baseB * 66 + dOff;
    const float* pRE = RE + baseE * 66 + dOff;

    for (int jt = 0; jt < 16; jt++) {
        const int j0 = jt * 64;
        __syncthreads();   // SYNC_A: prev PV done; first iter: QA ready

        // --- tile loads (512 threads) ---
        for (int idx = tid; idx < 1024; idx += 512) {
            int j = idx >> 4; int d4 = (idx & 15) << 2;
            float4 k4 = *(const float4*)&kptr[(size_t)(j0 + j) * 512 + d4];
            float* pk = &Ks[j * 66 + d4];
            *(float2*)&pk[0] = make_float2(k4.x, k4.y);
            *(float2*)&pk[2] = make_float2(k4.z, k4.w);
            float4 v4 = *(const float4*)&vptr[(size_t)(j0 + j) * 64 + d4];
            *(float4*)&Vs[j * 64 + d4] = v4;
        }
        const int rbBase = 1024 + j0 - i0 - 63;
        const int reBase = 1024 + i0 - j0 - 63;
        for (int idx = tid; idx < 2048; idx += 512) {
            int u = idx >> 4; int d4 = (idx & 15) << 2;
            int rb_r = rbBase + u; rb_r = (rb_r > 2047) ? 2047 : rb_r;
            int re_r = reBase + u; re_r = (re_r > 2047) ? 2047 : re_r;
            float4 b4 = *(const float4*)&g_rel[(size_t)rb_r * 64 + d4];
            float* prb = &RB[u * 66 + d4];
            *(float2*)&prb[0] = make_float2(b4.x, b4.y);
            *(float2*)&prb[2] = make_float2(b4.z, b4.w);
            float4 e4 = *(const float4*)&g_rel[(size_t)re_r * 64 + d4];
            float* pre = &RE[u * 66 + d4];
            *(float2*)&pre[0] = make_float2(e4.x, e4.y);
            *(float2*)&pre[2] = make_float2(e4.z, e4.w);
        }
        __syncthreads();   // SYNC_B: tiles ready

        // --- fused AC + B + E partial score (this half's 32 d), packed f32x2 ---
        ull s2[4][4];
        #pragma unroll
        for (int r = 0; r < 4; r++)
            #pragma unroll
            for (int c = 0; c < 4; c++) s2[r][c] = 0ULL;

        #pragma unroll 2
        for (int d = 0; d < 32; d += 2) {
            ull qa[4], k2[4], rb[7], re[7];
            #pragma unroll
            for (int r = 0; r < 4; r++) qa[r] = *(const ull*)&pQA[r * (16 * 66) + d];
            #pragma unroll
            for (int c = 0; c < 4; c++) k2[c] = *(const ull*)&pK[c * (16 * 66) + d];
            #pragma unroll
            for (int m = 0; m < 7; m++) {
                rb[m] = *(const ull*)&pRB[(m - 3) * (16 * 66) + d];
                re[m] = *(const ull*)&pRE[(m - 3) * (16 * 66) + d];
            }
            #pragma unroll
            for (int r = 0; r < 4; r++)
                #pragma unroll
                for (int c = 0; c < 4; c++) {
                    ull v = fma2(qa[r], k2[c], s2[r][c]);
                    v = fma2(qa[r], rb[c - r + 3], v);
                    s2[r][c] = fma2(k2[c], re[r - c + 3], v);
                }
        }
        // reduce packed pairs to scalars
        float s[4][4];
        #pragma unroll
        for (int r = 0; r < 4; r++)
            #pragma unroll
            for (int c = 0; c < 4; c++) {
                float2 v = unpack2(s2[r][c]);
                s[r][c] = v.x + v.y;
            }

        // half 1 publishes partials into Pm scratch
        if (h == 1) {
            #pragma unroll
            for (int r = 0; r < 4; r++) {
                float* prow = &Pm[(ty + 16 * r) * 66 + tx];
                #pragma unroll
                for (int c = 0; c < 4; c++) prow[16 * c] = s[r][c];
            }
        }
        __syncthreads();   // SYNC_C: partials visible

        if (h == 0) {
            // combine partials + relD, mask, softmax; publish P and scale
            float db[7];
            const float* pD = relD + (1024 + j0 - i0 + tx - ty);
            #pragma unroll
            for (int m = 0; m < 7; m++) db[m] = pD[16 * (m - 3)];

            #pragma unroll
            for (int r = 0; r < 4; r++) {
                float* prow = &Pm[(ty + 16 * r) * 66 + tx];
                #pragma unroll
                for (int c = 0; c < 4; c++)
                    s[r][c] += prow[16 * c] + db[c - r + 3];
            }
            #pragma unroll
            for (int c = 0; c < 4; c++) {
                if (j0 + tx + 16 * c >= seq) {
                    s[0][c] = -1e30f; s[1][c] = -1e30f; s[2][c] = -1e30f; s[3][c] = -1e30f;
                }
            }
            #pragma unroll
            for (int r = 0; r < 4; r++) {
                float mr = fmaxf(fmaxf(s[r][0], s[r][1]), fmaxf(s[r][2], s[r][3]));
                mr = fmaxf(mr, __shfl_xor_sync(0xffffffffu, mr, 1));
                mr = fmaxf(mr, __shfl_xor_sync(0xffffffffu, mr, 2));
                mr = fmaxf(mr, __shfl_xor_sync(0xffffffffu, mr, 4));
                mr = fmaxf(mr, __shfl_xor_sync(0xffffffffu, mr, 8));
                float mnew = fmaxf(m_r[r], mr);
                float scale = __expf(m_r[r] - mnew);
                float psum = 0.f;
                float* prow = &Pm[(ty + 16 * r) * 66 + tx];
                #pragma unroll
                for (int c = 0; c < 4; c++) {
                    float p = __expf(s[r][c] - mnew);
                    prow[16 * c] = p;
                    psum += p;
                }
                psum += __shfl_xor_sync(0xffffffffu, psum, 1);
                psum += __shfl_xor_sync(0xffffffffu, psum, 2);
                psum += __shfl_xor_sync(0xffffffffu, psum, 4);
                psum += __shfl_xor_sync(0xffffffffu, psum, 8);
                l_r[r] = l_r[r] * scale + psum;
                m_r[r] = mnew;
                ull sc2 = pack2(scale, scale);
                acc2[r][0] = mul2(acc2[r][0], sc2);
                acc2[r][1] = mul2(acc2[r][1], sc2);
                if (tx == 0) scS[ty + 16 * r] = scale;
            }
        }
        __syncthreads();   // SYNC_D: P + scales visible

        if (h == 1) {
            #pragma unroll
            for (int r = 0; r < 4; r++) {
                float sc = scS[ty + 16 * r];
                ull sc2 = pack2(sc, sc);
                acc2[r][0] = mul2(acc2[r][0], sc2);
                acc2[r][1] = mul2(acc2[r][1], sc2);
            }
        }

        // --- PV: this half's 32 jj, packed f32x2 ---
        const int jb = h * 32;
        #pragma unroll 2
        for (int jj = jb; jj < jb + 32; jj += 2) {
            ull v01 = *(const ull*)&Vs[jj * 64 + tx4];
            ull v23 = *(const ull*)&Vs[jj * 64 + tx4 + 2];
            ull w01 = *(const ull*)&Vs[(jj + 1) * 64 + tx4];
            ull w23 = *(const ull*)&Vs[(jj + 1) * 64 + tx4 + 2];
            #pragma unroll
            for (int r = 0; r < 4; r++) {
                float2 p = *(const float2*)&Pm[(ty + 16 * r) * 66 + jj];
                ull px = pack2(p.x, p.x);
                ull py = pack2(p.y, p.y);
                acc2[r][0] = fma2(px, v01, acc2[r][0]);
                acc2[r][1] = fma2(px, v23, acc2[r][1]);
                acc2[r][0] = fma2(py, w01, acc2[r][0]);
                acc2[r][1] = fma2(py, w23, acc2[r][1]);
            }
        }
    }

    // epilogue: combine halves through Vs buffer, then scale by 1/l
    __syncthreads();
    if (h == 1) {
        #pragma unroll
        for (int r = 0; r < 4; r++) {
            float2 a01 = unpack2(acc2[r][0]);
            float2 a23 = unpack2(acc2[r][1]);
            *(float4*)&Vs[(ty + 16 * r) * 64 + tx4] =
                make_float4(a01.x, a01.y, a23.x, a23.y);
        }
    }
    __syncthreads();
    if (h == 0) {
        #pragma unroll
        for (int r = 0; r < 4; r++) {
            float inv = 1.0f / l_r[r];
            float4 a2 = *(const float4*)&Vs[(ty + 16 * r) * 64 + tx4];
            float2 a01 = unpack2(acc2[r][0]);
            float2 a23 = unpack2(acc2[r][1]);
            int row = i0 + ty + 16 * r;
            float4 o;
            o.x = (a01.x + a2.x) * inv; o.y = (a01.y + a2.y) * inv;
            o.z = (a23.x + a2.z) * inv; o.w = (a23.y + a2.w) * inv;
            *(float4*)&out[(size_t)(b * 1024 + row) * 512 + n * 64 + tx4] = o;
        }
    }
}

// ---------------------------------------------------------------------------
extern "C" void kernel_launch(void* const* d_in, const int* in_sizes, int n_in,
                              void* d_out, int out_size) {
    const float* query    = (const float*)d_in[0];
    const float* key      = (const float*)d_in[1];
    const float* value    = (const float*)d_in[2];
    const float* w_q_w    = (const float*)d_in[3];
    const float* w_q_b    = (const float*)d_in[4];
    const float* w_v_w    = (const float*)d_in[5];
    const float* w_v_b    = (const float*)d_in[6];
    const float* w_r_w    = (const float*)d_in[7];
    const float* w_r_b    = (const float*)d_in[8];
    const float* r_r_bias = (const float*)d_in[9];
    const float* r_w_bias = (const float*)d_in[10];
    const int*   seq_len  = (const int*)d_in[11];
    float* out = (float*)d_out;

    const int rel_smem = (32768 + 4096) * 4;   // 147456
    cudaFuncSetAttribute(rel_kernel, cudaFuncAttributeMaxDynamicSharedMemorySize, rel_smem);
    rel_kernel<<<256, 256, rel_smem>>>(w_r_w, w_r_b);
    reld_kernel<<<64, 256>>>(r_r_bias, r_w_bias);

    proj_kernel<<<dim3(8, 64, 2), 256>>>(query, value, w_q_w, w_q_b, w_v_w, w_v_b);

    const int attn_smem = (3 * 64 * 66 + 2 * 128 * 66 + 64 * 64 + 64) * 4;   // 134912
    cudaFuncSetAttribute(attn_kernel, cudaFuncAttributeMaxDynamicSharedMemorySize, attn_smem);
    attn_kernel<<<dim3(16, 32), 512, attn_smem>>>(key, r_r_bias, seq_len, out);
}

// round 13
// speedup vs baseline: 1.2542x; 1.0615x over previous
#include <cuda_runtime.h>
#include <math.h>
#include <stdint.h>

typedef unsigned long long ull;

// Problem constants: B=4, L=1024, H=512, NH=8, HD=64, rel rows = 2048

__device__ float g_rel[2048 * 64];            // rel[t][d]
__device__ float g_relD[8 * 2048];            // delta_n . rel_t
__device__ float g_q[4 * 8 * 1024 * 64];      // [b][n][l][d]
__device__ float g_v[4 * 8 * 1024 * 64];

// ---------------------------------------------------------------------------
// Packed fp32x2 helpers (FFMA2)
// ---------------------------------------------------------------------------
__device__ __forceinline__ ull fma2(ull a, ull b, ull c) {
    ull d;
    asm("fma.rn.f32x2 %0, %1, %2, %3;" : "=l"(d) : "l"(a), "l"(b), "l"(c));
    return d;
}
__device__ __forceinline__ ull mul2(ull a, ull b) {
    ull d;
    asm("mul.rn.f32x2 %0, %1, %2;" : "=l"(d) : "l"(a), "l"(b));
    return d;
}
__device__ __forceinline__ ull pack2(float x, float y) {
    ull d;
    asm("mov.b64 %0, {%1, %2};" : "=l"(d) : "f"(x), "f"(y));
    return d;
}
__device__ __forceinline__ float2 unpack2(ull a) {
    float x, y;
    asm("mov.b64 {%0, %1}, %2;" : "=f"(x), "=f"(y) : "l"(a));
    return make_float2(x, y);
}

// ---------------------------------------------------------------------------
// Kernel 1: rel[t][d] = emb(t) @ w_r_w + w_r_b   (proven)
// ---------------------------------------------------------------------------
__global__ void __launch_bounds__(256) rel_kernel(const float* __restrict__ w_r_w,
                                                  const float* __restrict__ w_r_b) {
    extern __shared__ float rsm[];
    float* Wsm = rsm;            // 512*64
    float* Emb = Wsm + 32768;    // 8*512

    const int tid = threadIdx.x;
    const int r0 = blockIdx.x * 8;
    const float cc = (float)(-9.210340371976184 / 255.0);

    for (int idx = tid * 4; idx < 32768; idx += 1024)
        *(float4*)&Wsm[idx] = *(const float4*)&w_r_w[idx];

    for (int idx = tid; idx < 8 * 512; idx += 256) {
        int row = idx >> 9;
        int h = idx & 511;
        int t = (h < 256) ? h : (h - 256);
        float f = expf((float)t * cc);
        float ang = (float)(r0 + row - 1024) * f;
        Emb[idx] = (h < 256) ? sinf(ang) : cosf(ang);
    }
    __syncthreads();

    const int d = tid & 63;
    const int rl = tid >> 6;
    const float bias = w_r_b[d];
    #pragma unroll
    for (int rr = 0; rr < 2; rr++) {
        int row = rl + 4 * rr;
        float sum = bias;
        const float* e = &Emb[row * 512];
        #pragma unroll 8
        for (int h = 0; h < 512; h++)
            sum = fmaf(e[h], Wsm[h * 64 + d], sum);
        g_rel[(size_t)(r0 + row) * 64 + d] = sum;
    }
}

// ---------------------------------------------------------------------------
// Kernel 1b: g_relD[n][t] = (r_w_bias[n] - r_r_bias[n]) . g_rel[t]
// ---------------------------------------------------------------------------
__global__ void __launch_bounds__(256) reld_kernel(const float* __restrict__ rr_bias,
                                                   const float* __restrict__ rw_bias) {
    __shared__ float relS[32 * 64];
    __shared__ float dS[8 * 64];
    const int tid = threadIdx.x;
    const int t0 = blockIdx.x * 32;

    for (int i = tid; i < 512; i += 256)
        dS[i] = rw_bias[i] - rr_bias[i];
    for (int i = tid * 4; i < 2048; i += 1024)
        *(float4*)&relS[i] = *(const float4*)&g_rel[(size_t)t0 * 64 + i];
    __syncthreads();

    const int tl = tid >> 3, n = tid & 7;
    const float* dn = &dS[n * 64];
    const float* rrow = &relS[tl * 64];
    float s = 0.f;
    #pragma unroll 16
    for (int d = 0; d < 64; d++)
        s = fmaf(dn[d], rrow[d], s);
    g_relD[n * 2048 + t0 + tl] = s;
}

// ---------------------------------------------------------------------------
// Kernel 2: projections (proven R5 SGEMM)
// ---------------------------------------------------------------------------
__global__ void __launch_bounds__(256) proj_kernel(
    const float* __restrict__ q_in, const float* __restrict__ v_in,
    const float* __restrict__ wq, const float* __restrict__ bq,
    const float* __restrict__ wv, const float* __restrict__ bv) {

    const float* X;  const float* W;  const float* bias;  float* out;
    if (blockIdx.z == 0) { X = q_in; W = wq; bias = bq; out = g_q; }
    else                 { X = v_in; W = wv; bias = bv; out = g_v; }

    __shared__ float As[64][16];
    __shared__ float Bs[16][64];

    const int tid = threadIdx.x;
    const int tx = tid & 15, ty = tid >> 4;
    const int m0 = blockIdx.y * 64;
    const int n0 = blockIdx.x * 64;

    float acc[4][4] = {};

    for (int k0 = 0; k0 < 512; k0 += 16) {
        float4 av = *(const float4*)&X[(size_t)(m0 + (tid >> 2)) * 512 + k0 + (tid & 3) * 4];
        *(float4*)&As[tid >> 2][(tid & 3) * 4] = av;
        float4 bv4 = *(const float4*)&W[(size_t)(k0 + (tid >> 4)) * 512 + n0 + (tid & 15) * 4];
        *(float4*)&Bs[tid >> 4][(tid & 15) * 4] = bv4;
        __syncthreads();

        #pragma unroll
        for (int kk = 0; kk < 16; kk++) {
            float a[4];
            #pragma unroll
            for (int r = 0; r < 4; r++) a[r] = As[ty * 4 + r][kk];
            float4 b4 = *(const float4*)&Bs[kk][tx * 4];
            float b[4] = { b4.x, b4.y, b4.z, b4.w };
            #pragma unroll
            for (int r = 0; r < 4; r++)
                #pragma unroll
                for (int cc = 0; cc < 4; cc++)
                    acc[r][cc] = fmaf(a[r], b[cc], acc[r][cc]);
        }
        __syncthreads();
    }

    float4 bb = *(const float4*)&bias[n0 + tx * 4];
    const int n = blockIdx.x;
    #pragma unroll
    for (int r = 0; r < 4; r++) {
        int m = m0 + ty * 4 + r;
        int b = m >> 10, l = m & 1023;
        float4 o;
        o.x = acc[r][0] + bb.x;  o.y = acc[r][1] + bb.y;
        o.z = acc[r][2] + bb.z;  o.w = acc[r][3] + bb.w;
        *(float4*)&out[(size_t)((b * 8 + n) * 1024 + l) * 64 + tx * 4] = o;
    }
}

// ---------------------------------------------------------------------------
// Kernel 3: fused attention. 256 threads, tile 128 rows x 64 cols, 8x4
// fragments (rows ty+16r, cols tx+16c), full d=64 per thread, FFMA2 math.
// Band: rb index m = c-r+7 (11 slots), re index m = r-c+3.
// ---------------------------------------------------------------------------
__global__ void __launch_bounds__(256, 1) attn_kernel(
    const float* __restrict__ key,
    const float* __restrict__ r_r_bias,
    const int*   __restrict__ seq_len_p,
    float* __restrict__ out) {

    extern __shared__ float sm[];
    float* QA  = sm;                 // 128 x 66          [0,     8448)
    float* Ks  = QA + 8448;          //  64 x 66          [8448, 12672)
    float* Pm  = Ks + 4224;          // 128 x 66          [12672,21120)
    float* RB  = Pm + 8448;          // 192 x 66          [21120,33792)
    float* RE  = RB + 12672;         // 192 x 66          [33792,46464)
    float* Vs  = RE + 12672;         //  64 x 64          [46464,50560)

    const int tid = threadIdx.x;
    const int tx = tid & 15, ty = tid >> 4;
    const int tx4 = tx * 4;
    const int i0 = blockIdx.x * 128;
    const int bn = blockIdx.y;
    const int b = bn >> 3, n = bn & 7;
    const int seq = *seq_len_p;

    const float* qptr = g_q + (size_t)bn * 1024 * 64;
    const float* vptr = g_v + (size_t)bn * 1024 * 64;
    const float* kptr = key + (size_t)b * 1024 * 512 + n * 64;
    const float* relD = g_relD + n * 2048;

    // QA = q + r_r_bias  (128 rows)
    for (int idx = tid; idx < 2048; idx += 256) {
        int i = idx >> 4; int d4 = (idx & 15) << 2;
        float4 q4 = *(const float4*)&qptr[(size_t)(i0 + i) * 64 + d4];
        float4 rr = *(const float4*)&r_r_bias[n * 64 + d4];
        float* pa = &QA[i * 66 + d4];
        *(float2*)&pa[0] = make_float2(q4.x + rr.x, q4.y + rr.y);
        *(float2*)&pa[2] = make_float2(q4.z + rr.z, q4.w + rr.w);
    }

    float m_r[8], l_r[8];
    ull acc2[8][2];
    #pragma unroll
    for (int r = 0; r < 8; r++) {
        m_r[r] = -INFINITY; l_r[r] = 0.f;
        acc2[r][0] = 0ULL; acc2[r][1] = 0ULL;
    }

    const float* pQA = QA + ty * 66;                  // + r*1056 + d
    const float* pK  = Ks + tx * 66;                  // + c*1056 + d
    const float* pRB = RB + (tx - ty + 15) * 66;      // + m*1056 + d
    const float* pRE = RE + (ty - tx + 15) * 66;      // + m*1056 + d

    for (int jt = 0; jt < 16; jt++) {
        const int j0 = jt * 64;
        __syncthreads();   // SYNC_A: prev PV done; first iter: QA ready

        // --- K/V tile loads (64 rows) ---
        for (int idx = tid; idx < 1024; idx += 256) {
            int j = idx >> 4; int d4 = (idx & 15) << 2;
            float4 k4 = *(const float4*)&kptr[(size_t)(j0 + j) * 512 + d4];
            float* pk = &Ks[j * 66 + d4];
            *(float2*)&pk[0] = make_float2(k4.x, k4.y);
            *(float2*)&pk[2] = make_float2(k4.z, k4.w);
            float4 v4 = *(const float4*)&vptr[(size_t)(j0 + j) * 64 + d4];
            *(float4*)&Vs[j * 64 + d4] = v4;
        }
        // --- band loads (192 rows each) ---
        const int rbBase = 1024 + j0 - i0 - 127;
        const int reBase = 1024 + i0 - j0 - 63;
        for (int idx = tid; idx < 3072; idx += 256) {
            int u = idx >> 4; int d4 = (idx & 15) << 2;
            int rb_r = rbBase + u; rb_r = (rb_r > 2047) ? 2047 : rb_r;
            int re_r = reBase + u; re_r = (re_r > 2047) ? 2047 : re_r;
            float4 b4 = *(const float4*)&g_rel[(size_t)rb_r * 64 + d4];
            float* prb = &RB[u * 66 + d4];
            *(float2*)&prb[0] = make_float2(b4.x, b4.y);
            *(float2*)&prb[2] = make_float2(b4.z, b4.w);
            float4 e4 = *(const float4*)&g_rel[(size_t)re_r * 64 + d4];
            float* pre = &RE[u * 66 + d4];
            *(float2*)&pre[0] = make_float2(e4.x, e4.y);
            *(float2*)&pre[2] = make_float2(e4.z, e4.w);
        }
        __syncthreads();   // SYNC_B: tiles ready

        // --- fused AC + B + E score pass (full d), packed f32x2 ---
        ull s2[8][4];
        #pragma unroll
        for (int r = 0; r < 8; r++)
            #pragma unroll
            for (int c = 0; c < 4; c++) s2[r][c] = 0ULL;

        #pragma unroll 2
        for (int d = 0; d < 64; d += 2) {
            ull qa[8], k2[4], rb[11], re[11];
            #pragma unroll
            for (int r = 0; r < 8; r++) qa[r] = *(const ull*)&pQA[r * 1056 + d];
            #pragma unroll
            for (int c = 0; c < 4; c++) k2[c] = *(const ull*)&pK[c * 1056 + d];
            #pragma unroll
            for (int m = 0; m < 11; m++) {
                rb[m] = *(const ull*)&pRB[m * 1056 + d];
                re[m] = *(const ull*)&pRE[m * 1056 + d];
            }
            #pragma unroll
            for (int r = 0; r < 8; r++)
                #pragma unroll
                for (int c = 0; c < 4; c++) {
                    ull v = fma2(qa[r], k2[c], s2[r][c]);
                    v = fma2(qa[r], rb[c - r + 7], v);
                    s2[r][c] = fma2(k2[c], re[r - c + 3], v);
                }
        }

        // reduce packed pairs + relD
        float db[11];
        {
            const float* pD = relD + (1024 + j0 - i0 + tx - ty - 112);
            #pragma unroll
            for (int m = 0; m < 11; m++) db[m] = pD[16 * m];
        }
        float s[8][4];
        #pragma unroll
        for (int r = 0; r < 8; r++)
            #pragma unroll
            for (int c = 0; c < 4; c++) {
                float2 v = unpack2(s2[r][c]);
                s[r][c] = v.x + v.y + db[c - r + 7];
            }

        // --- mask + online softmax (row = ty+16r; 16 tx lanes per row,
        //     contained in a half-warp -> xor shuffles on bits 0..3) ---
        #pragma unroll
        for (int c = 0; c < 4; c++) {
            if (j0 + tx + 16 * c >= seq) {
                #pragma unroll
                for (int r = 0; r < 8; r++) s[r][c] = -1e30f;
            }
        }
        #pragma unroll
        for (int r = 0; r < 8; r++) {
            float mr = fmaxf(fmaxf(s[r][0], s[r][1]), fmaxf(s[r][2], s[r][3]));
            mr = fmaxf(mr, __shfl_xor_sync(0xffffffffu, mr, 1));
            mr = fmaxf(mr, __shfl_xor_sync(0xffffffffu, mr, 2));
            mr = fmaxf(mr, __shfl_xor_sync(0xffffffffu, mr, 4));
            mr = fmaxf(mr, __shfl_xor_sync(0xffffffffu, mr, 8));
            float mnew = fmaxf(m_r[r], mr);
            float scale = __expf(m_r[r] - mnew);
            float psum = 0.f;
            float* prow = &Pm[(ty + 16 * r) * 66 + tx];
            #pragma unroll
            for (int c = 0; c < 4; c++) {
                float p = __expf(s[r][c] - mnew);
                prow[16 * c] = p;
                psum += p;
            }
            psum += __shfl_xor_sync(0xffffffffu, psum, 1);
            psum += __shfl_xor_sync(0xffffffffu, psum, 2);
            psum += __shfl_xor_sync(0xffffffffu, psum, 4);
            psum += __shfl_xor_sync(0xffffffffu, psum, 8);
            l_r[r] = l_r[r] * scale + psum;
            m_r[r] = mnew;
            ull sc2 = pack2(scale, scale);
            acc2[r][0] = mul2(acc2[r][0], sc2);
            acc2[r][1] = mul2(acc2[r][1], sc2);
        }
        __syncthreads();   // SYNC_C: P visible

        // --- PV: all 64 jj, packed f32x2 ---
        #pragma unroll 2
        for (int jj = 0; jj < 64; jj += 2) {
            ull v01 = *(const ull*)&Vs[jj * 64 + tx4];
            ull v23 = *(const ull*)&Vs[jj * 64 + tx4 + 2];
            ull w01 = *(const ull*)&Vs[(jj + 1) * 64 + tx4];
            ull w23 = *(const ull*)&Vs[(jj + 1) * 64 + tx4 + 2];
            #pragma unroll
            for (int r = 0; r < 8; r++) {
                float2 p = *(const float2*)&Pm[(ty + 16 * r) * 66 + jj];
                ull px = pack2(p.x, p.x);
                ull py = pack2(p.y, p.y);
                acc2[r][0] = fma2(px, v01, acc2[r][0]);
                acc2[r][1] = fma2(px, v23, acc2[r][1]);
                acc2[r][0] = fma2(py, w01, acc2[r][0]);
                acc2[r][1] = fma2(py, w23, acc2[r][1]);
            }
        }
    }

    // epilogue: direct store (full d owned per thread)
    #pragma unroll
    for (int r = 0; r < 8; r++) {
        float inv = 1.0f / l_r[r];
        float2 a01 = unpack2(acc2[r][0]);
        float2 a23 = unpack2(acc2[r][1]);
        int row = i0 + ty + 16 * r;
        float4 o;
        o.x = a01.x * inv; o.y = a01.y * inv;
        o.z = a23.x * inv; o.w = a23.y * inv;
        *(float4*)&out[(size_t)(b * 1024 + row) * 512 + n * 64 + tx4] = o;
    }
}

// ---------------------------------------------------------------------------
extern "C" void kernel_launch(void* const* d_in, const int* in_sizes, int n_in,
                              void* d_out, int out_size) {
    const float* query    = (const float*)d_in[0];
    const float* key      = (const float*)d_in[1];
    const float* value    = (const float*)d_in[2];
    const float* w_q_w    = (const float*)d_in[3];
    const float* w_q_b    = (const float*)d_in[4];
    const float* w_v_w    = (const float*)d_in[5];
    const float* w_v_b    = (const float*)d_in[6];
    const float* w_r_w    = (const float*)d_in[7];
    const float* w_r_b    = (const float*)d_in[8];
    const float* r_r_bias = (const float*)d_in[9];
    const float* r_w_bias = (const float*)d_in[10];
    const int*   seq_len  = (const int*)d_in[11];
    float* out = (float*)d_out;

    const int rel_smem = (32768 + 4096) * 4;   // 147456
    cudaFuncSetAttribute(rel_kernel, cudaFuncAttributeMaxDynamicSharedMemorySize, rel_smem);
    rel_kernel<<<256, 256, rel_smem>>>(w_r_w, w_r_b);
    reld_kernel<<<64, 256>>>(r_r_bias, r_w_bias);

    proj_kernel<<<dim3(8, 64, 2), 256>>>(query, value, w_q_w, w_q_b, w_v_w, w_v_b);

    const int attn_smem = 50560 * 4;   // 202240
    cudaFuncSetAttribute(attn_kernel, cudaFuncAttributeMaxDynamicSharedMemorySize, attn_smem);
    attn_kernel<<<dim3(8, 32), 256, attn_smem>>>(key, r_r_bias, seq_len, out);
}

// round 15
// speedup vs baseline: 1.3604x; 1.0847x over previous
#include <cuda_runtime.h>
#include <math.h>
#include <stdint.h>

typedef unsigned long long ull;

// Problem constants: B=4, L=1024, H=512, NH=8, HD=64, rel rows = 2048

__device__ float g_rel[2048 * 64];            // rel[t][d]
__device__ float g_relD[8 * 2048];            // delta_n . rel_t
__device__ float g_q[4 * 8 * 1024 * 64];      // [b][n][l][d]
__device__ float g_v[4 * 8 * 1024 * 64];

// ---------------------------------------------------------------------------
// Packed fp32x2 helpers (FFMA2)
// ---------------------------------------------------------------------------
__device__ __forceinline__ ull fma2(ull a, ull b, ull c) {
    ull d;
    asm("fma.rn.f32x2 %0, %1, %2, %3;" : "=l"(d) : "l"(a), "l"(b), "l"(c));
    return d;
}
__device__ __forceinline__ ull mul2(ull a, ull b) {
    ull d;
    asm("mul.rn.f32x2 %0, %1, %2;" : "=l"(d) : "l"(a), "l"(b));
    return d;
}
__device__ __forceinline__ ull pack2(float x, float y) {
    ull d;
    asm("mov.b64 %0, {%1, %2};" : "=l"(d) : "f"(x), "f"(y));
    return d;
}
__device__ __forceinline__ float2 unpack2(ull a) {
    float x, y;
    asm("mov.b64 {%0, %1}, %2;" : "=f"(x), "=f"(y) : "l"(a));
    return make_float2(x, y);
}
// cp.async helpers (baseline PTX, sm_80+)
__device__ __forceinline__ void cp8(uint32_t dst, const void* src) {
    asm volatile("cp.async.ca.shared.global [%0], [%1], 8;" :: "r"(dst), "l"(src));
}
__device__ __forceinline__ void cp16(uint32_t dst, const void* src) {
    asm volatile("cp.async.cg.shared.global [%0], [%1], 16;" :: "r"(dst), "l"(src));
}
__device__ __forceinline__ void cp_commit() {
    asm volatile("cp.async.commit_group;" ::: "memory");
}
__device__ __forceinline__ void cp_wait0() {
    asm volatile("cp.async.wait_group 0;" ::: "memory");
}

// ---------------------------------------------------------------------------
// Kernel 1: rel[t][d] = emb(t) @ w_r_w + w_r_b   (proven)
// ---------------------------------------------------------------------------
__global__ void __launch_bounds__(256) rel_kernel(const float* __restrict__ w_r_w,
                                                  const float* __restrict__ w_r_b) {
    extern __shared__ float rsm[];
    float* Wsm = rsm;            // 512*64
    float* Emb = Wsm + 32768;    // 8*512

    const int tid = threadIdx.x;
    const int r0 = blockIdx.x * 8;
    const float cc = (float)(-9.210340371976184 / 255.0);

    for (int idx = tid * 4; idx < 32768; idx += 1024)
        *(float4*)&Wsm[idx] = *(const float4*)&w_r_w[idx];

    for (int idx = tid; idx < 8 * 512; idx += 256) {
        int row = idx >> 9;
        int h = idx & 511;
        int t = (h < 256) ? h : (h - 256);
        float f = expf((float)t * cc);
        float ang = (float)(r0 + row - 1024) * f;
        Emb[idx] = (h < 256) ? sinf(ang) : cosf(ang);
    }
    __syncthreads();

    const int d = tid & 63;
    const int rl = tid >> 6;
    const float bias = w_r_b[d];
    #pragma unroll
    for (int rr = 0; rr < 2; rr++) {
        int row = rl + 4 * rr;
        float sum = bias;
        const float* e = &Emb[row * 512];
        #pragma unroll 8
        for (int h = 0; h < 512; h++)
            sum = fmaf(e[h], Wsm[h * 64 + d], sum);
        g_rel[(size_t)(r0 + row) * 64 + d] = sum;
    }
}

// ---------------------------------------------------------------------------
// Kernel 1b: g_relD[n][t] = (r_w_bias[n] - r_r_bias[n]) . g_rel[t]
// ---------------------------------------------------------------------------
__global__ void __launch_bounds__(256) reld_kernel(const float* __restrict__ rr_bias,
                                                   const float* __restrict__ rw_bias) {
    __shared__ float relS[32 * 64];
    __shared__ float dS[8 * 64];
    const int tid = threadIdx.x;
    const int t0 = blockIdx.x * 32;

    for (int i = tid; i < 512; i += 256)
        dS[i] = rw_bias[i] - rr_bias[i];
    for (int i = tid * 4; i < 2048; i += 1024)
        *(float4*)&relS[i] = *(const float4*)&g_rel[(size_t)t0 * 64 + i];
    __syncthreads();

    const int tl = tid >> 3, n = tid & 7;
    const float* dn = &dS[n * 64];
    const float* rrow = &relS[tl * 64];
    float s = 0.f;
    #pragma unroll 16
    for (int d = 0; d < 64; d++)
        s = fmaf(dn[d], rrow[d], s);
    g_relD[n * 2048 + t0 + tl] = s;
}

// ---------------------------------------------------------------------------
// Kernel 2: projections (proven R5 SGEMM)
// ---------------------------------------------------------------------------
__global__ void __launch_bounds__(256) proj_kernel(
    const float* __restrict__ q_in, const float* __restrict__ v_in,
    const float* __restrict__ wq, const float* __restrict__ bq,
    const float* __restrict__ wv, const float* __restrict__ bv) {

    const float* X;  const float* W;  const float* bias;  float* out;
    if (blockIdx.z == 0) { X = q_in; W = wq; bias = bq; out = g_q; }
    else                 { X = v_in; W = wv; bias = bv; out = g_v; }

    __shared__ float As[64][16];
    __shared__ float Bs[16][64];

    const int tid = threadIdx.x;
    const int tx = tid & 15, ty = tid >> 4;
    const int m0 = blockIdx.y * 64;
    const int n0 = blockIdx.x * 64;

    float acc[4][4] = {};

    for (int k0 = 0; k0 < 512; k0 += 16) {
        float4 av = *(const float4*)&X[(size_t)(m0 + (tid >> 2)) * 512 + k0 + (tid & 3) * 4];
        *(float4*)&As[tid >> 2][(tid & 3) * 4] = av;
        float4 bv4 = *(const float4*)&W[(size_t)(k0 + (tid >> 4)) * 512 + n0 + (tid & 15) * 4];
        *(float4*)&Bs[tid >> 4][(tid & 15) * 4] = bv4;
        __syncthreads();

        #pragma unroll
        for (int kk = 0; kk < 16; kk++) {
            float a[4];
            #pragma unroll
            for (int r = 0; r < 4; r++) a[r] = As[ty * 4 + r][kk];
            float4 b4 = *(const float4*)&Bs[kk][tx * 4];
            float b[4] = { b4.x, b4.y, b4.z, b4.w };
            #pragma unroll
            for (int r = 0; r < 4; r++)
                #pragma unroll
                for (int cc = 0; cc < 4; cc++)
                    acc[r][cc] = fmaf(a[r], b[cc], acc[r][cc]);
        }
        __syncthreads();
    }

    float4 bb = *(const float4*)&bias[n0 + tx * 4];
    const int n = blockIdx.x;
    #pragma unroll
    for (int r = 0; r < 4; r++) {
        int m = m0 + ty * 4 + r;
        int b = m >> 10, l = m & 1023;
        float4 o;
        o.x = acc[r][0] + bb.x;  o.y = acc[r][1] + bb.y;
        o.z = acc[r][2] + bb.z;  o.w = acc[r][3] + bb.w;
        *(float4*)&out[(size_t)((b * 8 + n) * 1024 + l) * 64 + tx * 4] = o;
    }
}

// ---------------------------------------------------------------------------
// Kernel 3: fused attention. 256 threads, 128x64 tile, 8x4 frags, FFMA2,
// cp.async software pipeline (next jt's K/bands/V loaded behind softmax+PV),
// Vs double-buffered, 2 full barriers + 1 syncwarp per jt.
// ---------------------------------------------------------------------------
__global__ void __launch_bounds__(256, 1) attn_kernel(
    const float* __restrict__ key,
    const float* __restrict__ r_r_bias,
    const int*   __restrict__ seq_len_p,
    float* __restrict__ out) {

    extern __shared__ float sm[];
    float* QA  = sm;                 // 128 x 66          [0,     8448)
    float* Ks  = QA + 8448;          //  64 x 66          [8448, 12672)
    float* Pm  = Ks + 4224;          // 128 x 66          [12672,21120)
    float* RB  = Pm + 8448;          // 192 x 66          [21120,33792)
    float* RE  = RB + 12672;         // 192 x 66          [33792,46464)
    float* Vs0 = RE + 12672;         //  64 x 64          [46464,50560)
    float* Vs1 = Vs0 + 4096;         //  64 x 64          [50560,54656)

    const int tid = threadIdx.x;
    const int tx = tid & 15, ty = tid >> 4;
    const int tx4 = tx * 4;
    const int i0 = blockIdx.x * 128;
    const int bn = blockIdx.y;
    const int b = bn >> 3, n = bn & 7;
    const int seq = *seq_len_p;

    const float* qptr = g_q + (size_t)bn * 1024 * 64;
    const float* vptr = g_v + (size_t)bn * 1024 * 64;
    const float* kptr = key + (size_t)b * 1024 * 512 + n * 64;
    const float* relD = g_relD + n * 2048;

    const uint32_t ksA  = (uint32_t)__cvta_generic_to_shared(Ks);
    const uint32_t rbA  = (uint32_t)__cvta_generic_to_shared(RB);
    const uint32_t reA  = (uint32_t)__cvta_generic_to_shared(RE);
    const uint32_t vs0A = (uint32_t)__cvta_generic_to_shared(Vs0);
    const uint32_t vs1A = (uint32_t)__cvta_generic_to_shared(Vs1);

    // async tile loader: K (8B chunks, stride-66), bands (8B), V (16B, stride-64)
    auto load_tiles = [&](int j0n, uint32_t vsDst) {
        // K: 64 rows x 32 8B-chunks = 2048
        for (int idx = tid; idx < 2048; idx += 256) {
            int j = idx >> 5, ch = idx & 31;
            cp8(ksA + (uint32_t)(j * 66 + ch * 2) * 4,
                kptr + (size_t)(j0n + j) * 512 + ch * 2);
        }
        // V: 64 rows x 16 16B-chunks = 1024
        for (int idx = tid; idx < 1024; idx += 256) {
            int j = idx >> 4, ch = idx & 15;
            cp16(vsDst + (uint32_t)(j * 64 + ch * 4) * 4,
                 vptr + (size_t)(j0n + j) * 64 + ch * 4);
        }
        // bands: 192 rows x 32 8B-chunks = 6144 each
        const int rbBase = 1024 + j0n - i0 - 127;
        const int reBase = 1024 + i0 - j0n - 63;
        for (int idx = tid; idx < 6144; idx += 256) {
            int u = idx >> 5, ch = idx & 31;
            int rb_r = rbBase + u; rb_r = (rb_r > 2047) ? 2047 : rb_r;
            cp8(rbA + (uint32_t)(u * 66 + ch * 2) * 4,
                g_rel + (size_t)rb_r * 64 + ch * 2);
        }
        for (int idx = tid; idx < 6144; idx += 256) {
            int u = idx >> 5, ch = idx & 31;
            int re_r = reBase + u; re_r = (re_r > 2047) ? 2047 : re_r;
            cp8(reA + (uint32_t)(u * 66 + ch * 2) * 4,
                g_rel + (size_t)re_r * 64 + ch * 2);
        }
    };

    // QA = q + r_r_bias  (128 rows)
    for (int idx = tid; idx < 2048; idx += 256) {
        int i = idx >> 4; int d4 = (idx & 15) << 2;
        float4 q4 = *(const float4*)&qptr[(size_t)(i0 + i) * 64 + d4];
        float4 rr = *(const float4*)&r_r_bias[n * 64 + d4];
        float* pa = &QA[i * 66 + d4];
        *(float2*)&pa[0] = make_float2(q4.x + rr.x, q4.y + rr.y);
        *(float2*)&pa[2] = make_float2(q4.z + rr.z, q4.w + rr.w);
    }
    // prologue: async-load jt=0 tiles, wait
    load_tiles(0, vs0A);
    cp_commit();
    cp_wait0();
    __syncthreads();

    float m_r[8], l_r[8];
    ull acc2[8][2];
    #pragma unroll
    for (int r = 0; r < 8; r++) {
        m_r[r] = -INFINITY; l_r[r] = 0.f;
        acc2[r][0] = 0ULL; acc2[r][1] = 0ULL;
    }

    const float* pQA = QA + ty * 66;                  // + r*1056 + d
    const float* pK  = Ks + tx * 66;                  // + c*1056 + d
    const float* pRB = RB + (tx - ty + 15) * 66;      // + m*1056 + d
    const float* pRE = RE + (ty - tx + 15) * 66;      // + m*1056 + d

    for (int jt = 0; jt < 16; jt++) {
        const int j0 = jt * 64;
        const float* Vsb = (jt & 1) ? Vs1 : Vs0;
        const uint32_t vsNext = (jt & 1) ? vs0A : vs1A;

        // prefetch relD band (consumed after score pass)
        float db[11];
        {
            const float* pD = relD + (1024 + j0 - i0 + tx - ty - 112);
            #pragma unroll
            for (int m = 0; m < 11; m++) db[m] = pD[16 * m];
        }

        // --- fused AC + B + E score pass (full d), packed f32x2 ---
        ull s2[8][4];
        #pragma unroll
        for (int r = 0; r < 8; r++)
            #pragma unroll
            for (int c = 0; c < 4; c++) s2[r][c] = 0ULL;

        #pragma unroll 2
        for (int d = 0; d < 64; d += 2) {
            ull qa[8], k2[4], rb[11], re[11];
            #pragma unroll
            for (int r = 0; r < 8; r++) qa[r] = *(const ull*)&pQA[r * 1056 + d];
            #pragma unroll
            for (int c = 0; c < 4; c++) k2[c] = *(const ull*)&pK[c * 1056 + d];
            #pragma unroll
            for (int m = 0; m < 11; m++) {
                rb[m] = *(const ull*)&pRB[m * 1056 + d];
                re[m] = *(const ull*)&pRE[m * 1056 + d];
            }
            #pragma unroll
            for (int r = 0; r < 8; r++)
                #pragma unroll
                for (int c = 0; c < 4; c++) {
                    ull v = fma2(qa[r], k2[c], s2[r][c]);
                    v = fma2(qa[r], rb[c - r + 7], v);
                    s2[r][c] = fma2(k2[c], re[r - c + 3], v);
                }
        }
        __syncthreads();   // SYNC1: all warps done reading Ks/RB/RE

        // kick off next jt's loads (drain behind softmax + PV)
        if (jt < 15) {
            load_tiles(j0 + 64, vsNext);
            cp_commit();
        }

        // reduce packed pairs + relD
        float s[8][4];
        #pragma unroll
        for (int r = 0; r < 8; r++)
            #pragma unroll
            for (int c = 0; c < 4; c++) {
                float2 v = unpack2(s2[r][c]);
                s[r][c] = v.x + v.y + db[c - r + 7];
            }

        // --- mask + online softmax ---
        #pragma unroll
        for (int c = 0; c < 4; c++) {
            if (j0 + tx + 16 * c >= seq) {
                #pragma unroll
                for (int r = 0; r < 8; r++) s[r][c] = -1e30f;
            }
        }
        #pragma unroll
        for (int r = 0; r < 8; r++) {
            float mr = fmaxf(fmaxf(s[r][0], s[r][1]), fmaxf(s[r][2], s[r][3]));
            mr = fmaxf(mr, __shfl_xor_sync(0xffffffffu, mr, 1));
            mr = fmaxf(mr, __shfl_xor_sync(0xffffffffu, mr, 2));
            mr = fmaxf(mr, __shfl_xor_sync(0xffffffffu, mr, 4));
            mr = fmaxf(mr, __shfl_xor_sync(0xffffffffu, mr, 8));
            float mnew = fmaxf(m_r[r], mr);
            float scale = __expf(m_r[r] - mnew);
            float psum = 0.f;
            float* prow = &Pm[(ty + 16 * r) * 66 + tx];
            #pragma unroll
            for (int c = 0; c < 4; c++) {
                float p = __expf(s[r][c] - mnew);
                prow[16 * c] = p;
                psum += p;
            }
            psum += __shfl_xor_sync(0xffffffffu, psum, 1);
            psum += __shfl_xor_sync(0xffffffffu, psum, 2);
            psum += __shfl_xor_sync(0xffffffffu, psum, 4);
            psum += __shfl_xor_sync(0xffffffffu, psum, 8);
            l_r[r] = l_r[r] * scale + psum;
            m_r[r] = mnew;
            ull sc2 = pack2(scale, scale);
            acc2[r][0] = mul2(acc2[r][0], sc2);
            acc2[r][1] = mul2(acc2[r][1], sc2);
        }
        // Pm rows (ty+16r) written and read by the SAME half-warp -> warp sync
        __syncwarp(0xffffffffu);

        // --- PV: all 64 jj, packed f32x2 ---
        #pragma unroll 2
        for (int jj = 0; jj < 64; jj += 2) {
            ull v01 = *(const ull*)&Vsb[jj * 64 + tx4];
            ull v23 = *(const ull*)&Vsb[jj * 64 + tx4 + 2];
            ull w01 = *(const ull*)&Vsb[(jj + 1) * 64 + tx4];
            ull w23 = *(const ull*)&Vsb[(jj + 1) * 64 + tx4 + 2];
            #pragma unroll
            for (int r = 0; r < 8; r++) {
                float2 p = *(const float2*)&Pm[(ty + 16 * r) * 66 + jj];
                ull px = pack2(p.x, p.x);
                ull py = pack2(p.y, p.y);
                acc2[r][0] = fma2(px, v01, acc2[r][0]);
                acc2[r][1] = fma2(px, v23, acc2[r][1]);
                acc2[r][0] = fma2(py, w01, acc2[r][0]);
                acc2[r][1] = fma2(py, w23, acc2[r][1]);
            }
        }

        cp_wait0();        // async tiles for next jt landed
        __syncthreads();   // SYNC2: visible to all; Pm free for next softmax
    }

    // epilogue: direct store (full d owned per thread)
    #pragma unroll
    for (int r = 0; r < 8; r++) {
        float inv = 1.0f / l_r[r];
        float2 a01 = unpack2(acc2[r][0]);
        float2 a23 = unpack2(acc2[r][1]);
        int row = i0 + ty + 16 * r;
        float4 o;
        o.x = a01.x * inv; o.y = a01.y * inv;
        o.z = a23.x * inv; o.w = a23.y * inv;
        *(float4*)&out[(size_t)(b * 1024 + row) * 512 + n * 64 + tx4] = o;
    }
}

// ---------------------------------------------------------------------------
extern "C" void kernel_launch(void* const* d_in, const int* in_sizes, int n_in,
                              void* d_out, int out_size) {
    const float* query    = (const float*)d_in[0];
    const float* key      = (const float*)d_in[1];
    const float* value    = (const float*)d_in[2];
    const float* w_q_w    = (const float*)d_in[3];
    const float* w_q_b    = (const float*)d_in[4];
    const float* w_v_w    = (const float*)d_in[5];
    const float* w_v_b    = (const float*)d_in[6];
    const float* w_r_w    = (const float*)d_in[7];
    const float* w_r_b    = (const float*)d_in[8];
    const float* r_r_bias = (const float*)d_in[9];
    const float* r_w_bias = (const float*)d_in[10];
    const int*   seq_len  = (const int*)d_in[11];
    float* out = (float*)d_out;

    const int rel_smem = (32768 + 4096) * 4;   // 147456
    cudaFuncSetAttribute(rel_kernel, cudaFuncAttributeMaxDynamicSharedMemorySize, rel_smem);
    rel_kernel<<<256, 256, rel_smem>>>(w_r_w, w_r_b);
    reld_kernel<<<64, 256>>>(r_r_bias, r_w_bias);

    proj_kernel<<<dim3(8, 64, 2), 256>>>(query, value, w_q_w, w_q_b, w_v_w, w_v_b);

    const int attn_smem = 54656 * 4;   // 218624
    cudaFuncSetAttribute(attn_kernel, cudaFuncAttributeMaxDynamicSharedMemorySize, attn_smem);
    attn_kernel<<<dim3(8, 32), 256, attn_smem>>>(key, r_r_bias, seq_len, out);
}